// round 1
// baseline (speedup 1.0000x reference)
#include <cuda_runtime.h>
#include <math.h>
#include <stdint.h>

#define Bq 2
#define SEQ 2048
#define Dm 1024
#define NCx 77
#define DCx 768
#define Hh 16
#define DHd 64
#define FFd 4096
#define SCALE_ATTN 0.125f
#define EPS_LN 1e-5f
#define MROWS (Bq*SEQ)          // 4096
#define CROWS (Bq*NCx)          // 154

// ---------------- scratch (static device memory; allocation-free) ----------------
__device__ float g_h[(size_t)MROWS*Dm];
__device__ float g_q[(size_t)MROWS*Dm];
__device__ float g_k[(size_t)MROWS*Dm];
__device__ float g_v[(size_t)MROWS*Dm];
__device__ float g_att[(size_t)MROWS*Dm];
__device__ float g_s[(size_t)Bq*Hh*SEQ*SEQ];      // 512 MB, reused for cross scores
__device__ float g_p[(size_t)MROWS*2*FFd];        // 128 MB
__device__ float g_t[(size_t)MROWS*FFd];          // 64 MB

// ---------------- elementwise copy ----------------
__global__ void copy_kernel(const float* __restrict__ src, float* __restrict__ dst, int n4) {
    int i = blockIdx.x * blockDim.x + threadIdx.x;
    if (i < n4) {
        reinterpret_cast<float4*>(dst)[i] = reinterpret_cast<const float4*>(src)[i];
    }
}

// ---------------- layernorm: one block per row, D=1024 ----------------
__global__ void ln_kernel(const float* __restrict__ x, const float* __restrict__ g,
                          const float* __restrict__ b, float* __restrict__ out) {
    int row = blockIdx.x;
    const float* xr = x + (size_t)row * Dm;
    float s = 0.f, ss = 0.f;
    for (int i = threadIdx.x; i < Dm; i += 256) {
        float v = xr[i];
        s += v; ss += v * v;
    }
    __shared__ float rs[256], rss[256];
    rs[threadIdx.x] = s; rss[threadIdx.x] = ss;
    __syncthreads();
    for (int st = 128; st > 0; st >>= 1) {
        if (threadIdx.x < st) { rs[threadIdx.x] += rs[threadIdx.x+st]; rss[threadIdx.x] += rss[threadIdx.x+st]; }
        __syncthreads();
    }
    float mu  = rs[0] * (1.0f / Dm);
    float var = rss[0] * (1.0f / Dm) - mu * mu;
    float inv = rsqrtf(var + EPS_LN);
    float* orow = out + (size_t)row * Dm;
    for (int i = threadIdx.x; i < Dm; i += 256) {
        orow[i] = (xr[i] - mu) * inv * g[i] + b[i];
    }
}

// ---------------- generic dense GEMM: C = A(MxK) * B(KxN) [+bias] [+res] ----------------
// 64x64 tile, BK=16, 256 threads, 4x4 per thread. K must be a multiple of 16.
__global__ void gemm_kernel(const float* __restrict__ A, const float* __restrict__ Bm,
                            const float* __restrict__ bias, const float* __restrict__ res,
                            float* __restrict__ C, int M, int K, int Nn) {
    __shared__ float As[64][17];   // [m][k]
    __shared__ float Bs[16][64];   // [k][n]
    int bm = blockIdx.y * 64, bn = blockIdx.x * 64;
    int tx = threadIdx.x & 15, ty = threadIdx.x >> 4;
    float acc[4][4] = {};
    for (int k0 = 0; k0 < K; k0 += 16) {
        #pragma unroll
        for (int i = 0; i < 4; i++) {
            int idx = threadIdx.x + i * 256;
            int r = idx >> 4, kk = idx & 15;       // A: 64 rows x 16 k
            int gr = bm + r;
            As[r][kk] = (gr < M) ? A[(size_t)gr * K + k0 + kk] : 0.f;
            int kb = idx >> 6, c = idx & 63;       // B: 16 k x 64 n
            int gc = bn + c;
            Bs[kb][c] = (gc < Nn) ? Bm[(size_t)(k0 + kb) * Nn + gc] : 0.f;
        }
        __syncthreads();
        #pragma unroll
        for (int kk = 0; kk < 16; kk++) {
            float a[4], bb[4];
            #pragma unroll
            for (int i = 0; i < 4; i++) a[i]  = As[ty*4+i][kk];
            #pragma unroll
            for (int j = 0; j < 4; j++) bb[j] = Bs[kk][tx*4+j];
            #pragma unroll
            for (int i = 0; i < 4; i++)
                #pragma unroll
                for (int j = 0; j < 4; j++)
                    acc[i][j] += a[i] * bb[j];
        }
        __syncthreads();
    }
    #pragma unroll
    for (int i = 0; i < 4; i++) {
        int gr = bm + ty*4 + i;
        if (gr >= M) continue;
        #pragma unroll
        for (int j = 0; j < 4; j++) {
            int gc = bn + tx*4 + j;
            if (gc >= Nn) continue;
            float v = acc[i][j];
            if (bias) v += bias[gc];
            if (res)  v += res[(size_t)gr * Nn + gc];
            C[(size_t)gr * Nn + gc] = v;
        }
    }
}

// ---------------- batched attention scores: S[bh,i,j] = SCALE * sum_d Q[b,i,h,d] K[b,j,h,d] ----------------
__global__ void scores_kernel(const float* __restrict__ q, const float* __restrict__ k,
                              float* __restrict__ s, int nk) {
    int bh = blockIdx.z;
    int b = bh / Hh, h = bh % Hh;
    int i0 = blockIdx.y * 64, j0 = blockIdx.x * 64;
    __shared__ float Qs[64][65];
    __shared__ float Ks[64][65];
    const float* qb = q + (size_t)b * SEQ * Dm + h * DHd;
    const float* kb = k + (size_t)b * nk  * Dm + h * DHd;
    for (int t = threadIdx.x; t < 64*64; t += 256) {
        int r = t >> 6, c = t & 63;
        Qs[r][c] = qb[(size_t)(i0 + r) * Dm + c];                 // i0+r < SEQ always
        Ks[r][c] = (j0 + r < nk) ? kb[(size_t)(j0 + r) * Dm + c] : 0.f;
    }
    __syncthreads();
    int tx = threadIdx.x & 15, ty = threadIdx.x >> 4;
    float acc[4][4] = {};
    #pragma unroll 16
    for (int kk = 0; kk < 64; kk++) {
        float a[4], bb[4];
        #pragma unroll
        for (int i = 0; i < 4; i++) a[i]  = Qs[ty*4+i][kk];
        #pragma unroll
        for (int j = 0; j < 4; j++) bb[j] = Ks[tx*4+j][kk];
        #pragma unroll
        for (int i = 0; i < 4; i++)
            #pragma unroll
            for (int j = 0; j < 4; j++)
                acc[i][j] += a[i] * bb[j];
    }
    #pragma unroll
    for (int i = 0; i < 4; i++) {
        int gi = i0 + ty*4 + i;
        #pragma unroll
        for (int j = 0; j < 4; j++) {
            int gj = j0 + tx*4 + j;
            if (gj < nk)
                s[((size_t)bh * SEQ + gi) * nk + gj] = acc[i][j] * SCALE_ATTN;
        }
    }
}

// ---------------- row softmax over last dim ----------------
__global__ void softmax_kernel(float* __restrict__ s, int len) {
    float* r = s + (size_t)blockIdx.x * len;
    __shared__ float red[256];
    float mx = -3.4e38f;
    for (int i = threadIdx.x; i < len; i += 256) mx = fmaxf(mx, r[i]);
    red[threadIdx.x] = mx; __syncthreads();
    for (int st = 128; st > 0; st >>= 1) {
        if (threadIdx.x < st) red[threadIdx.x] = fmaxf(red[threadIdx.x], red[threadIdx.x+st]);
        __syncthreads();
    }
    mx = red[0];
    __syncthreads();
    float sum = 0.f;
    for (int i = threadIdx.x; i < len; i += 256) {
        float e = expf(r[i] - mx);
        r[i] = e;
        sum += e;
    }
    red[threadIdx.x] = sum; __syncthreads();
    for (int st = 128; st > 0; st >>= 1) {
        if (threadIdx.x < st) red[threadIdx.x] += red[threadIdx.x+st];
        __syncthreads();
    }
    float inv = 1.f / red[0];
    for (int i = threadIdx.x; i < len; i += 256) r[i] *= inv;
}

// ---------------- batched AV: out[b,i,h,d] = sum_j S[bh,i,j] V[b,j,h,d] ----------------
__global__ void av_kernel(const float* __restrict__ s, const float* __restrict__ v,
                          float* __restrict__ out, int nk) {
    int bh = blockIdx.z;
    int b = bh / Hh, h = bh % Hh;
    int i0 = blockIdx.y * 64;
    __shared__ float Ss[64][17];   // [i][k]
    __shared__ float Vs[16][65];   // [k][d]
    const float* sb = s + ((size_t)bh * SEQ + i0) * nk;
    const float* vb = v + (size_t)b * nk * Dm + h * DHd;
    int tx = threadIdx.x & 15, ty = threadIdx.x >> 4;
    float acc[4][4] = {};
    for (int k0 = 0; k0 < nk; k0 += 16) {
        for (int t = threadIdx.x; t < 64*16; t += 256) {
            int r = t >> 4, c = t & 15;
            Ss[r][c] = (k0 + c < nk) ? sb[(size_t)r * nk + k0 + c] : 0.f;
        }
        for (int t = threadIdx.x; t < 16*64; t += 256) {
            int r = t >> 6, c = t & 63;
            Vs[r][c] = (k0 + r < nk) ? vb[(size_t)(k0 + r) * Dm + c] : 0.f;
        }
        __syncthreads();
        #pragma unroll
        for (int kk = 0; kk < 16; kk++) {
            float a[4], bb[4];
            #pragma unroll
            for (int i = 0; i < 4; i++) a[i]  = Ss[ty*4+i][kk];
            #pragma unroll
            for (int j = 0; j < 4; j++) bb[j] = Vs[kk][tx*4+j];
            #pragma unroll
            for (int i = 0; i < 4; i++)
                #pragma unroll
                for (int j = 0; j < 4; j++)
                    acc[i][j] += a[i] * bb[j];
        }
        __syncthreads();
    }
    float* ob = out + (size_t)(b * SEQ + i0) * Dm + h * DHd;
    #pragma unroll
    for (int i = 0; i < 4; i++)
        #pragma unroll
        for (int j = 0; j < 4; j++)
            ob[(size_t)(ty*4+i) * Dm + tx*4 + j] = acc[i][j];
}

// ---------------- GEGLU: t = val * gelu_exact(gate) ----------------
__global__ void geglu_kernel(const float* __restrict__ p, float* __restrict__ t) {
    size_t idx = (size_t)blockIdx.x * blockDim.x + threadIdx.x;
    if (idx < (size_t)MROWS * FFd) {
        size_t row = idx / FFd, col = idx % FFd;
        float val  = p[row * (2*FFd) + col];
        float gate = p[row * (2*FFd) + FFd + col];
        float ge = 0.5f * gate * (1.f + erff(gate * 0.70710678118654752f));
        t[idx] = val * ge;
    }
}

// ---------------- launch ----------------
extern "C" void kernel_launch(void* const* d_in, const int* in_sizes, int n_in,
                              void* d_out, int out_size) {
    const float* x      = (const float*)d_in[0];
    const float* ctx    = (const float*)d_in[1];
    const float* w1_q   = (const float*)d_in[2];
    const float* w1_k   = (const float*)d_in[3];
    const float* w1_v   = (const float*)d_in[4];
    const float* w1_o   = (const float*)d_in[5];
    const float* b1_o   = (const float*)d_in[6];
    const float* w2_q   = (const float*)d_in[7];
    const float* w2_k   = (const float*)d_in[8];
    const float* w2_v   = (const float*)d_in[9];
    const float* w2_o   = (const float*)d_in[10];
    const float* b2_o   = (const float*)d_in[11];
    const float* ln1_g  = (const float*)d_in[12];
    const float* ln1_b  = (const float*)d_in[13];
    const float* ln2_g  = (const float*)d_in[14];
    const float* ln2_b  = (const float*)d_in[15];
    const float* ln3_g  = (const float*)d_in[16];
    const float* ln3_b  = (const float*)d_in[17];
    const float* ff_w1  = (const float*)d_in[18];
    const float* ff_b1  = (const float*)d_in[19];
    const float* ff_w2  = (const float*)d_in[20];
    const float* ff_b2  = (const float*)d_in[21];
    float* xbuf = (float*)d_out;

    float *hB, *qB, *kB, *vB, *attB, *sB, *pB, *tB;
    cudaGetSymbolAddress((void**)&hB,   g_h);
    cudaGetSymbolAddress((void**)&qB,   g_q);
    cudaGetSymbolAddress((void**)&kB,   g_k);
    cudaGetSymbolAddress((void**)&vB,   g_v);
    cudaGetSymbolAddress((void**)&attB, g_att);
    cudaGetSymbolAddress((void**)&sB,   g_s);
    cudaGetSymbolAddress((void**)&pB,   g_p);
    cudaGetSymbolAddress((void**)&tB,   g_t);

    dim3 g1024(Dm/64, MROWS/64);           // dense (M=4096, N=1024)
    dim3 gScoresSelf(SEQ/64, SEQ/64, Bq*Hh);
    dim3 gScoresCross((NCx+63)/64, SEQ/64, Bq*Hh);
    dim3 gAV(1, SEQ/64, Bq*Hh);

    // x -> xbuf (running residual stream, also the final output)
    copy_kernel<<<(MROWS*Dm/4 + 255)/256, 256>>>(x, xbuf, MROWS*Dm/4);

    // ---- self attention ----
    ln_kernel<<<MROWS, 256>>>(xbuf, ln1_g, ln1_b, hB);
    gemm_kernel<<<g1024, 256>>>(hB, w1_q, nullptr, nullptr, qB, MROWS, Dm, Dm);
    gemm_kernel<<<g1024, 256>>>(hB, w1_k, nullptr, nullptr, kB, MROWS, Dm, Dm);
    gemm_kernel<<<g1024, 256>>>(hB, w1_v, nullptr, nullptr, vB, MROWS, Dm, Dm);
    scores_kernel<<<gScoresSelf, 256>>>(qB, kB, sB, SEQ);
    softmax_kernel<<<Bq*Hh*SEQ, 256>>>(sB, SEQ);
    av_kernel<<<gAV, 256>>>(sB, vB, attB, SEQ);
    gemm_kernel<<<g1024, 256>>>(attB, w1_o, b1_o, xbuf, xbuf, MROWS, Dm, Dm);

    // ---- cross attention ----
    ln_kernel<<<MROWS, 256>>>(xbuf, ln2_g, ln2_b, hB);
    gemm_kernel<<<g1024, 256>>>(hB, w2_q, nullptr, nullptr, qB, MROWS, Dm, Dm);
    dim3 gKV(Dm/64, (CROWS+63)/64);
    gemm_kernel<<<gKV, 256>>>(ctx, w2_k, nullptr, nullptr, kB, CROWS, DCx, Dm);
    gemm_kernel<<<gKV, 256>>>(ctx, w2_v, nullptr, nullptr, vB, CROWS, DCx, Dm);
    scores_kernel<<<gScoresCross, 256>>>(qB, kB, sB, NCx);
    softmax_kernel<<<Bq*Hh*SEQ, 256>>>(sB, NCx);
    av_kernel<<<gAV, 256>>>(sB, vB, attB, NCx);
    gemm_kernel<<<g1024, 256>>>(attB, w2_o, b2_o, xbuf, xbuf, MROWS, Dm, Dm);

    // ---- GEGLU FFN ----
    ln_kernel<<<MROWS, 256>>>(xbuf, ln3_g, ln3_b, hB);
    dim3 gFF1(2*FFd/64, MROWS/64);
    gemm_kernel<<<gFF1, 256>>>(hB, ff_w1, ff_b1, nullptr, pB, MROWS, Dm, 2*FFd);
    geglu_kernel<<<((size_t)MROWS*FFd + 255)/256, 256>>>(pB, tB);
    dim3 gFF2(Dm/64, MROWS/64);
    gemm_kernel<<<gFF2, 256>>>(tB, ff_w2, ff_b2, xbuf, xbuf, MROWS, FFd, Dm);
}

// round 2
// speedup vs baseline: 2.4040x; 2.4040x over previous
#include <cuda_runtime.h>
#include <math.h>
#include <stdint.h>

#define Bq 2
#define SEQ 2048
#define Dm 1024
#define NCx 77
#define DCx 768
#define Hh 16
#define DHd 64
#define FFd 4096
#define SCALE_ATTN 0.125f
#define EPS_LN 1e-5f
#define MROWS (Bq*SEQ)          // 4096
#define CROWS (Bq*NCx)          // 154

// ---------------- scratch (static device memory; allocation-free) ----------------
__device__ float g_h[(size_t)MROWS*Dm];
__device__ float g_q[(size_t)MROWS*Dm];
__device__ float g_k[(size_t)MROWS*Dm];
__device__ float g_v[(size_t)MROWS*Dm];
__device__ float g_att[(size_t)MROWS*Dm];
__device__ float g_s[(size_t)Bq*Hh*SEQ*SEQ];      // 512 MB, reused for cross scores
__device__ float g_p[(size_t)MROWS*2*FFd];        // 128 MB
__device__ float g_t[(size_t)MROWS*FFd];          // 64 MB

// ---------------- helpers ----------------
__device__ __forceinline__ uint32_t f2tf32(float f) {
    uint32_t u;
    asm("cvt.rna.tf32.f32 %0, %1;" : "=r"(u) : "f"(f));
    return u;
}

__device__ __forceinline__ void mma_tf32(float c[4],
                                         uint32_t a0, uint32_t a1, uint32_t a2, uint32_t a3,
                                         uint32_t b0, uint32_t b1) {
    asm volatile(
        "mma.sync.aligned.m16n8k8.row.col.f32.tf32.tf32.f32 "
        "{%0,%1,%2,%3}, {%4,%5,%6,%7}, {%8,%9}, {%0,%1,%2,%3};"
        : "+f"(c[0]), "+f"(c[1]), "+f"(c[2]), "+f"(c[3])
        : "r"(a0), "r"(a1), "r"(a2), "r"(a3), "r"(b0), "r"(b1));
}

// ---------------- tf32 tensor-core GEMM ----------------
// C[z] = scale * (A[z](MxK) * B[z](KxN or NxK if TRANSB)) + bias + res
// Block: 128x128 tile, BK=32, 256 threads (8 warps, 2x4 warp grid, 64x32 per warp).
// Batch offsets: off = (z/zdiv)*s_b + (z%zdiv)*s_h  (for A, B, C separately).
#define SM_STRIDE 136

template<bool TRANSB>
__global__ __launch_bounds__(256)
void mma_gemm(const float* __restrict__ A, const float* __restrict__ B,
              const float* __restrict__ bias, const float* __restrict__ res,
              float* __restrict__ C,
              int M, int N, int K, int lda, int ldb, int ldc,
              long sAb, long sAh, long sBb, long sBh, long sCb, long sCh,
              int zdiv, float scale) {
    __shared__ uint32_t As[32][SM_STRIDE];
    __shared__ uint32_t Bs[32][SM_STRIDE];

    int z = blockIdx.z;
    const float* Ab = A + (size_t)(z / zdiv) * sAb + (size_t)(z % zdiv) * sAh;
    const float* Bb = B + (size_t)(z / zdiv) * sBb + (size_t)(z % zdiv) * sBh;
    float*       Cb = C + (size_t)(z / zdiv) * sCb + (size_t)(z % zdiv) * sCh;

    int bm = blockIdx.y * 128, bn = blockIdx.x * 128;
    int tid  = threadIdx.x;
    int warp = tid >> 5, lane = tid & 31;
    int grp = lane >> 2, tig = lane & 3;
    int wm = (warp >> 2) * 64;   // 0 or 64
    int wn = (warp & 3) * 32;    // 0,32,64,96

    float acc[4][4][4] = {};

    bool ldaVec = ((lda & 3) == 0);
    bool ldbVec = ((ldb & 3) == 0);

    for (int k0 = 0; k0 < K; k0 += 32) {
        // ---- load A chunk -> As[k][m] (tf32) ----
        if (k0 + 32 <= K && ldaVec) {
            int kq = tid & 7, r0 = tid >> 3;
            #pragma unroll
            for (int stp = 0; stp < 4; stp++) {
                int row = r0 + stp * 32;
                float4 v = make_float4(0.f, 0.f, 0.f, 0.f);
                if (bm + row < M)
                    v = *reinterpret_cast<const float4*>(Ab + (size_t)(bm + row) * lda + k0 + kq * 4);
                As[kq*4+0][row] = f2tf32(v.x);
                As[kq*4+1][row] = f2tf32(v.y);
                As[kq*4+2][row] = f2tf32(v.z);
                As[kq*4+3][row] = f2tf32(v.w);
            }
        } else {
            for (int idx = tid; idx < 128 * 32; idx += 256) {
                int m = idx >> 5, kk = idx & 31;
                float v = (bm + m < M && k0 + kk < K)
                          ? Ab[(size_t)(bm + m) * lda + k0 + kk] : 0.f;
                As[kk][m] = f2tf32(v);
            }
        }
        // ---- load B chunk -> Bs[k][n] (tf32) ----
        if (TRANSB) {
            if (k0 + 32 <= K && ldbVec) {
                int kq = tid & 7, n0 = tid >> 3;
                #pragma unroll
                for (int stp = 0; stp < 4; stp++) {
                    int n = n0 + stp * 32;
                    float4 v = make_float4(0.f, 0.f, 0.f, 0.f);
                    if (bn + n < N)
                        v = *reinterpret_cast<const float4*>(Bb + (size_t)(bn + n) * ldb + k0 + kq * 4);
                    Bs[kq*4+0][n] = f2tf32(v.x);
                    Bs[kq*4+1][n] = f2tf32(v.y);
                    Bs[kq*4+2][n] = f2tf32(v.z);
                    Bs[kq*4+3][n] = f2tf32(v.w);
                }
            } else {
                for (int idx = tid; idx < 128 * 32; idx += 256) {
                    int kk = idx & 31, n = idx >> 5;
                    float v = (bn + n < N && k0 + kk < K)
                              ? Bb[(size_t)(bn + n) * ldb + k0 + kk] : 0.f;
                    Bs[kk][n] = f2tf32(v);
                }
            }
        } else {
            if (k0 + 32 <= K && bn + 128 <= N && ldbVec) {
                int n4 = tid & 31, kr0 = tid >> 5;
                #pragma unroll
                for (int stp = 0; stp < 4; stp++) {
                    int kk = kr0 + stp * 8;
                    float4 v = *reinterpret_cast<const float4*>(Bb + (size_t)(k0 + kk) * ldb + bn + n4 * 4);
                    Bs[kk][n4*4+0] = f2tf32(v.x);
                    Bs[kk][n4*4+1] = f2tf32(v.y);
                    Bs[kk][n4*4+2] = f2tf32(v.z);
                    Bs[kk][n4*4+3] = f2tf32(v.w);
                }
            } else {
                for (int idx = tid; idx < 128 * 32; idx += 256) {
                    int n = idx & 127, kk = idx >> 7;
                    float v = (k0 + kk < K && bn + n < N)
                              ? Bb[(size_t)(k0 + kk) * ldb + bn + n] : 0.f;
                    Bs[kk][n] = f2tf32(v);
                }
            }
        }
        __syncthreads();

        // ---- compute: 4 k-steps of 8 ----
        #pragma unroll
        for (int ks = 0; ks < 32; ks += 8) {
            uint32_t a[4][4], b[4][2];
            #pragma unroll
            for (int mf = 0; mf < 4; mf++) {
                int m = wm + mf * 16 + grp;
                a[mf][0] = As[ks + tig    ][m];
                a[mf][1] = As[ks + tig    ][m + 8];
                a[mf][2] = As[ks + tig + 4][m];
                a[mf][3] = As[ks + tig + 4][m + 8];
            }
            #pragma unroll
            for (int nf = 0; nf < 4; nf++) {
                int n = wn + nf * 8 + grp;
                b[nf][0] = Bs[ks + tig    ][n];
                b[nf][1] = Bs[ks + tig + 4][n];
            }
            #pragma unroll
            for (int mf = 0; mf < 4; mf++)
                #pragma unroll
                for (int nf = 0; nf < 4; nf++)
                    mma_tf32(acc[mf][nf], a[mf][0], a[mf][1], a[mf][2], a[mf][3],
                             b[nf][0], b[nf][1]);
        }
        __syncthreads();
    }

    // ---- epilogue ----
    #pragma unroll
    for (int mf = 0; mf < 4; mf++) {
        #pragma unroll
        for (int nf = 0; nf < 4; nf++) {
            int r0 = bm + wm + mf * 16 + grp;
            int c0 = bn + wn + nf * 8 + tig * 2;
            #pragma unroll
            for (int e = 0; e < 4; e++) {
                int r = r0 + (e >> 1) * 8;
                int c = c0 + (e & 1);
                if (r < M && c < N) {
                    float v = acc[mf][nf][e] * scale;
                    if (bias) v += bias[c];
                    if (res)  v += res[(size_t)r * ldc + c];
                    Cb[(size_t)r * ldc + c] = v;
                }
            }
        }
    }
}

// ---------------- elementwise copy ----------------
__global__ void copy_kernel(const float* __restrict__ src, float* __restrict__ dst, int n4) {
    int i = blockIdx.x * blockDim.x + threadIdx.x;
    if (i < n4) {
        reinterpret_cast<float4*>(dst)[i] = reinterpret_cast<const float4*>(src)[i];
    }
}

// ---------------- layernorm: one block per row, D=1024 ----------------
__global__ void ln_kernel(const float* __restrict__ x, const float* __restrict__ g,
                          const float* __restrict__ b, float* __restrict__ out) {
    int row = blockIdx.x;
    const float* xr = x + (size_t)row * Dm;
    float s = 0.f, ss = 0.f;
    for (int i = threadIdx.x; i < Dm; i += 256) {
        float v = xr[i];
        s += v; ss += v * v;
    }
    __shared__ float rs[256], rss[256];
    rs[threadIdx.x] = s; rss[threadIdx.x] = ss;
    __syncthreads();
    for (int st = 128; st > 0; st >>= 1) {
        if (threadIdx.x < st) { rs[threadIdx.x] += rs[threadIdx.x+st]; rss[threadIdx.x] += rss[threadIdx.x+st]; }
        __syncthreads();
    }
    float mu  = rs[0] * (1.0f / Dm);
    float var = rss[0] * (1.0f / Dm) - mu * mu;
    float inv = rsqrtf(var + EPS_LN);
    float* orow = out + (size_t)row * Dm;
    for (int i = threadIdx.x; i < Dm; i += 256) {
        orow[i] = (xr[i] - mu) * inv * g[i] + b[i];
    }
}

// ---------------- fallback fp32 GEMM (small cross-KV proj only) ----------------
__global__ void gemm_kernel(const float* __restrict__ A, const float* __restrict__ Bm,
                            const float* __restrict__ bias, const float* __restrict__ res,
                            float* __restrict__ C, int M, int K, int Nn) {
    __shared__ float As[64][17];
    __shared__ float Bs[16][64];
    int bm = blockIdx.y * 64, bn = blockIdx.x * 64;
    int tx = threadIdx.x & 15, ty = threadIdx.x >> 4;
    float acc[4][4] = {};
    for (int k0 = 0; k0 < K; k0 += 16) {
        #pragma unroll
        for (int i = 0; i < 4; i++) {
            int idx = threadIdx.x + i * 256;
            int r = idx >> 4, kk = idx & 15;
            int gr = bm + r;
            As[r][kk] = (gr < M) ? A[(size_t)gr * K + k0 + kk] : 0.f;
            int kb = idx >> 6, c = idx & 63;
            int gc = bn + c;
            Bs[kb][c] = (gc < Nn) ? Bm[(size_t)(k0 + kb) * Nn + gc] : 0.f;
        }
        __syncthreads();
        #pragma unroll
        for (int kk = 0; kk < 16; kk++) {
            float a[4], bb[4];
            #pragma unroll
            for (int i = 0; i < 4; i++) a[i]  = As[ty*4+i][kk];
            #pragma unroll
            for (int j = 0; j < 4; j++) bb[j] = Bs[kk][tx*4+j];
            #pragma unroll
            for (int i = 0; i < 4; i++)
                #pragma unroll
                for (int j = 0; j < 4; j++)
                    acc[i][j] += a[i] * bb[j];
        }
        __syncthreads();
    }
    #pragma unroll
    for (int i = 0; i < 4; i++) {
        int gr = bm + ty*4 + i;
        if (gr >= M) continue;
        #pragma unroll
        for (int j = 0; j < 4; j++) {
            int gc = bn + tx*4 + j;
            if (gc >= Nn) continue;
            float v = acc[i][j];
            if (bias) v += bias[gc];
            if (res)  v += res[(size_t)gr * Nn + gc];
            C[(size_t)gr * Nn + gc] = v;
        }
    }
}

// ---------------- row softmax over last dim ----------------
__global__ void softmax_kernel(float* __restrict__ s, int len) {
    float* r = s + (size_t)blockIdx.x * len;
    __shared__ float red[256];
    float mx = -3.4e38f;
    for (int i = threadIdx.x; i < len; i += 256) mx = fmaxf(mx, r[i]);
    red[threadIdx.x] = mx; __syncthreads();
    for (int st = 128; st > 0; st >>= 1) {
        if (threadIdx.x < st) red[threadIdx.x] = fmaxf(red[threadIdx.x], red[threadIdx.x+st]);
        __syncthreads();
    }
    mx = red[0];
    __syncthreads();
    float sum = 0.f;
    for (int i = threadIdx.x; i < len; i += 256) {
        float e = expf(r[i] - mx);
        r[i] = e;
        sum += e;
    }
    red[threadIdx.x] = sum; __syncthreads();
    for (int st = 128; st > 0; st >>= 1) {
        if (threadIdx.x < st) red[threadIdx.x] += red[threadIdx.x+st];
        __syncthreads();
    }
    float inv = 1.f / red[0];
    for (int i = threadIdx.x; i < len; i += 256) r[i] *= inv;
}

// ---------------- GEGLU: t = val * gelu_exact(gate) ----------------
__global__ void geglu_kernel(const float* __restrict__ p, float* __restrict__ t) {
    size_t idx = (size_t)blockIdx.x * blockDim.x + threadIdx.x;
    if (idx < (size_t)MROWS * FFd) {
        size_t row = idx / FFd, col = idx % FFd;
        float val  = p[row * (2*FFd) + col];
        float gate = p[row * (2*FFd) + FFd + col];
        float ge = 0.5f * gate * (1.f + erff(gate * 0.70710678118654752f));
        t[idx] = val * ge;
    }
}

// ---------------- launch ----------------
extern "C" void kernel_launch(void* const* d_in, const int* in_sizes, int n_in,
                              void* d_out, int out_size) {
    const float* x      = (const float*)d_in[0];
    const float* ctx    = (const float*)d_in[1];
    const float* w1_q   = (const float*)d_in[2];
    const float* w1_k   = (const float*)d_in[3];
    const float* w1_v   = (const float*)d_in[4];
    const float* w1_o   = (const float*)d_in[5];
    const float* b1_o   = (const float*)d_in[6];
    const float* w2_q   = (const float*)d_in[7];
    const float* w2_k   = (const float*)d_in[8];
    const float* w2_v   = (const float*)d_in[9];
    const float* w2_o   = (const float*)d_in[10];
    const float* b2_o   = (const float*)d_in[11];
    const float* ln1_g  = (const float*)d_in[12];
    const float* ln1_b  = (const float*)d_in[13];
    const float* ln2_g  = (const float*)d_in[14];
    const float* ln2_b  = (const float*)d_in[15];
    const float* ln3_g  = (const float*)d_in[16];
    const float* ln3_b  = (const float*)d_in[17];
    const float* ff_w1  = (const float*)d_in[18];
    const float* ff_b1  = (const float*)d_in[19];
    const float* ff_w2  = (const float*)d_in[20];
    const float* ff_b2  = (const float*)d_in[21];
    float* xbuf = (float*)d_out;

    float *hB, *qB, *kB, *vB, *attB, *sB, *pB, *tB;
    cudaGetSymbolAddress((void**)&hB,   g_h);
    cudaGetSymbolAddress((void**)&qB,   g_q);
    cudaGetSymbolAddress((void**)&kB,   g_k);
    cudaGetSymbolAddress((void**)&vB,   g_v);
    cudaGetSymbolAddress((void**)&attB, g_att);
    cudaGetSymbolAddress((void**)&sB,   g_s);
    cudaGetSymbolAddress((void**)&pB,   g_p);
    cudaGetSymbolAddress((void**)&tB,   g_t);

    // dense grids (128x128 tiles)
    dim3 gD(Dm/128, MROWS/128, 1);          // 4096x1024
    dim3 gFF1(2*FFd/128, MROWS/128, 1);     // 4096x8192
    dim3 gFF2(Dm/128, MROWS/128, 1);        // 4096x1024 (K=4096)
    dim3 gScoresSelf(SEQ/128, SEQ/128, Bq*Hh);
    dim3 gScoresCross(1, SEQ/128, Bq*Hh);
    dim3 gAV(1, SEQ/128, Bq*Hh);

    copy_kernel<<<(MROWS*Dm/4 + 255)/256, 256>>>(x, xbuf, MROWS*Dm/4);

    // ---- self attention ----
    ln_kernel<<<MROWS, 256>>>(xbuf, ln1_g, ln1_b, hB);
    mma_gemm<false><<<gD, 256>>>(hB, w1_q, nullptr, nullptr, qB, MROWS, Dm, Dm,
                                 Dm, Dm, Dm, 0,0,0,0,0,0, 1, 1.f);
    mma_gemm<false><<<gD, 256>>>(hB, w1_k, nullptr, nullptr, kB, MROWS, Dm, Dm,
                                 Dm, Dm, Dm, 0,0,0,0,0,0, 1, 1.f);
    mma_gemm<false><<<gD, 256>>>(hB, w1_v, nullptr, nullptr, vB, MROWS, Dm, Dm,
                                 Dm, Dm, Dm, 0,0,0,0,0,0, 1, 1.f);
    // scores: S[bh] = scale * Q K^T   (batched over 32 bh)
    mma_gemm<true><<<gScoresSelf, 256>>>(qB, kB, nullptr, nullptr, sB,
                                 SEQ, SEQ, DHd, Dm, Dm, SEQ,
                                 (long)SEQ*Dm, DHd, (long)SEQ*Dm, DHd,
                                 (long)Hh*SEQ*SEQ, (long)SEQ*SEQ, Hh, SCALE_ATTN);
    softmax_kernel<<<Bq*Hh*SEQ, 256>>>(sB, SEQ);
    // AV: out[bh] = S V
    mma_gemm<false><<<gAV, 256>>>(sB, vB, nullptr, nullptr, attB,
                                 SEQ, DHd, SEQ, SEQ, Dm, Dm,
                                 (long)Hh*SEQ*SEQ, (long)SEQ*SEQ, (long)SEQ*Dm, DHd,
                                 (long)SEQ*Dm, DHd, Hh, 1.f);
    mma_gemm<false><<<gD, 256>>>(attB, w1_o, b1_o, xbuf, xbuf, MROWS, Dm, Dm,
                                 Dm, Dm, Dm, 0,0,0,0,0,0, 1, 1.f);

    // ---- cross attention ----
    ln_kernel<<<MROWS, 256>>>(xbuf, ln2_g, ln2_b, hB);
    mma_gemm<false><<<gD, 256>>>(hB, w2_q, nullptr, nullptr, qB, MROWS, Dm, Dm,
                                 Dm, Dm, Dm, 0,0,0,0,0,0, 1, 1.f);
    dim3 gKV(Dm/64, (CROWS+63)/64);
    gemm_kernel<<<gKV, 256>>>(ctx, w2_k, nullptr, nullptr, kB, CROWS, DCx, Dm);
    gemm_kernel<<<gKV, 256>>>(ctx, w2_v, nullptr, nullptr, vB, CROWS, DCx, Dm);
    mma_gemm<true><<<gScoresCross, 256>>>(qB, kB, nullptr, nullptr, sB,
                                 SEQ, NCx, DHd, Dm, Dm, NCx,
                                 (long)SEQ*Dm, DHd, (long)NCx*Dm, DHd,
                                 (long)Hh*SEQ*NCx, (long)SEQ*NCx, Hh, SCALE_ATTN);
    softmax_kernel<<<Bq*Hh*SEQ, 256>>>(sB, NCx);
    mma_gemm<false><<<gAV, 256>>>(sB, vB, nullptr, nullptr, attB,
                                 SEQ, DHd, NCx, NCx, Dm, Dm,
                                 (long)Hh*SEQ*NCx, (long)SEQ*NCx, (long)NCx*Dm, DHd,
                                 (long)SEQ*Dm, DHd, Hh, 1.f);
    mma_gemm<false><<<gD, 256>>>(attB, w2_o, b2_o, xbuf, xbuf, MROWS, Dm, Dm,
                                 Dm, Dm, Dm, 0,0,0,0,0,0, 1, 1.f);

    // ---- GEGLU FFN ----
    ln_kernel<<<MROWS, 256>>>(xbuf, ln3_g, ln3_b, hB);
    mma_gemm<false><<<gFF1, 256>>>(hB, ff_w1, ff_b1, nullptr, pB, MROWS, 2*FFd, Dm,
                                 Dm, 2*FFd, 2*FFd, 0,0,0,0,0,0, 1, 1.f);
    geglu_kernel<<<((size_t)MROWS*FFd + 255)/256, 256>>>(pB, tB);
    mma_gemm<false><<<gFF2, 256>>>(tB, ff_w2, ff_b2, xbuf, xbuf, MROWS, Dm, FFd,
                                 FFd, Dm, Dm, 0,0,0,0,0,0, 1, 1.f);
}

// round 3
// speedup vs baseline: 3.9344x; 1.6366x over previous
#include <cuda_runtime.h>
#include <math.h>
#include <stdint.h>

#define Bq 2
#define SEQ 2048
#define Dm 1024
#define NCx 77
#define DCx 768
#define Hh 16
#define DHd 64
#define FFd 4096
#define SCALE_ATTN 0.125f
#define EPS_LN 1e-5f
#define MROWS (Bq*SEQ)          // 4096
#define CROWS (Bq*NCx)          // 154

// ---------------- scratch (static device memory; allocation-free) ----------------
__device__ float g_h[(size_t)MROWS*Dm];
__device__ float g_q[(size_t)MROWS*Dm];
__device__ float g_k[(size_t)MROWS*Dm];
__device__ float g_v[(size_t)MROWS*Dm];
__device__ float g_att[(size_t)MROWS*Dm];
__device__ float g_s[(size_t)Bq*Hh*SEQ*NCx];      // cross scores only now (~20MB)
__device__ float g_p[(size_t)MROWS*2*FFd];        // 128 MB
__device__ float g_t[(size_t)MROWS*FFd];          // 64 MB

// ---------------- helpers ----------------
__device__ __forceinline__ uint32_t f2tf32(float f) {
    uint32_t u;
    asm("cvt.rna.tf32.f32 %0, %1;" : "=r"(u) : "f"(f));
    return u;
}
__device__ __forceinline__ float ex2f(float x) {
    float y;
    asm("ex2.approx.f32 %0, %1;" : "=f"(y) : "f"(x));
    return y;
}
__device__ __forceinline__ void mma_tf32(float c[4],
                                         uint32_t a0, uint32_t a1, uint32_t a2, uint32_t a3,
                                         uint32_t b0, uint32_t b1) {
    asm volatile(
        "mma.sync.aligned.m16n8k8.row.col.f32.tf32.tf32.f32 "
        "{%0,%1,%2,%3}, {%4,%5,%6,%7}, {%8,%9}, {%0,%1,%2,%3};"
        : "+f"(c[0]), "+f"(c[1]), "+f"(c[2]), "+f"(c[3])
        : "r"(a0), "r"(a1), "r"(a2), "r"(a3), "r"(b0), "r"(b1));
}
__device__ __forceinline__ void cpa16(uint32_t dst, const void* src) {
    asm volatile("cp.async.cg.shared.global [%0], [%1], 16;" :: "r"(dst), "l"(src));
}
#define CP_COMMIT() asm volatile("cp.async.commit_group;")
#define CP_WAIT1()  asm volatile("cp.async.wait_group 1;")

// ================= fast dense GEMM (NN, exact 128-multiples) =================
// C = A(MxK)*B(KxN) [+bias] [+res], row-major. BM=BN=128, BK=32.
// 128 threads, 4 warps (2x2), 64x64 per warp. 3-stage cp.async pipeline.
#define ASTR 36
#define BSTR 132
#define ABUF (128*ASTR)
#define BBUF (32*BSTR)
#define GF_SMEM ((3*ABUF + 3*BBUF)*4)

__global__ __launch_bounds__(128, 2)
void gemm_fast(const float* __restrict__ A, const float* __restrict__ B,
               const float* __restrict__ bias, const float* __restrict__ res,
               float* __restrict__ C, int M, int N, int K) {
    extern __shared__ float sm[];
    float* As = sm;
    float* Bs = sm + 3*ABUF;
    int bm = blockIdx.y * 128, bn = blockIdx.x * 128;
    int tid = threadIdx.x, warp = tid >> 5, lane = tid & 31;
    int grp = lane >> 2, tig = lane & 3;
    int wm = (warp >> 1) * 64, wn = (warp & 1) * 64;
    uint32_t sAu = (uint32_t)__cvta_generic_to_shared(As);
    uint32_t sBu = (uint32_t)__cvta_generic_to_shared(Bs);
    int niter = K >> 5;

    float acc[4][8][4] = {};

    // tile loader: A -> As[buf][m][k] (natural), B -> Bs[buf][k][n] (natural)
    auto loadTile = [&](int it, int buf) {
        int k0 = it * 32;
        const float* Ap = A + (size_t)bm * K + k0;
        #pragma unroll
        for (int i = 0; i < 8; i++) {
            int c = tid + i * 128;
            int r = c >> 3, kq = c & 7;
            cpa16(sAu + (uint32_t)(buf*ABUF + r*ASTR + kq*4) * 4,
                  Ap + (size_t)r * K + kq * 4);
        }
        const float* Bp = B + (size_t)k0 * N + bn;
        #pragma unroll
        for (int i = 0; i < 8; i++) {
            int c = tid + i * 128;
            int kr = c >> 5, nq = c & 31;
            cpa16(sBu + (uint32_t)(buf*BBUF + kr*BSTR + nq*4) * 4,
                  Bp + (size_t)kr * N + nq * 4);
        }
    };

    loadTile(0, 0); CP_COMMIT();
    loadTile(1, 1); CP_COMMIT();

    for (int it = 0; it < niter; ++it) {
        CP_WAIT1();
        __syncthreads();
        if (it + 2 < niter) { loadTile(it + 2, (it + 2) % 3); CP_COMMIT(); }
        else { CP_COMMIT(); }   // empty group keeps wait-count invariant

        const float* Ab = As + (it % 3) * ABUF;
        const float* Bb = Bs + (it % 3) * BBUF;
        #pragma unroll
        for (int ks = 0; ks < 32; ks += 8) {
            uint32_t af[4][4], bf[8][2];
            #pragma unroll
            for (int mf = 0; mf < 4; mf++) {
                const float* p = Ab + (wm + mf*16 + grp) * ASTR;
                af[mf][0] = __float_as_uint(p[ks + tig]);
                af[mf][1] = __float_as_uint(p[8*ASTR + ks + tig]);
                af[mf][2] = __float_as_uint(p[ks + tig + 4]);
                af[mf][3] = __float_as_uint(p[8*ASTR + ks + tig + 4]);
            }
            #pragma unroll
            for (int nf = 0; nf < 8; nf++) {
                int n = wn + nf*8 + grp;
                bf[nf][0] = __float_as_uint(Bb[(ks + tig    ) * BSTR + n]);
                bf[nf][1] = __float_as_uint(Bb[(ks + tig + 4) * BSTR + n]);
            }
            #pragma unroll
            for (int mf = 0; mf < 4; mf++)
                #pragma unroll
                for (int nf = 0; nf < 8; nf++)
                    mma_tf32(acc[mf][nf], af[mf][0], af[mf][1], af[mf][2], af[mf][3],
                             bf[nf][0], bf[nf][1]);
        }
        __syncthreads();
    }

    // epilogue
    #pragma unroll
    for (int mf = 0; mf < 4; mf++) {
        #pragma unroll
        for (int nf = 0; nf < 8; nf++) {
            int r = bm + wm + mf*16 + grp;
            int c = bn + wn + nf*8 + tig*2;
            float2 v0 = make_float2(acc[mf][nf][0], acc[mf][nf][1]);
            float2 v1 = make_float2(acc[mf][nf][2], acc[mf][nf][3]);
            if (bias) {
                float2 bb = *(const float2*)(bias + c);
                v0.x += bb.x; v0.y += bb.y; v1.x += bb.x; v1.y += bb.y;
            }
            if (res) {
                float2 r0 = *(const float2*)(res + (size_t)r * N + c);
                float2 r1 = *(const float2*)(res + (size_t)(r+8) * N + c);
                v0.x += r0.x; v0.y += r0.y; v1.x += r1.x; v1.y += r1.y;
            }
            *(float2*)(C + (size_t)r * N + c) = v0;
            *(float2*)(C + (size_t)(r+8) * N + c) = v1;
        }
    }
}

// ================= flash attention (self-attn, DH=64, 128x128 tiles) =========
// 256 threads, 8 warps; warp handles 16 Q-rows x 128 KV-cols.
#define QSTR 68
#define PSTR 132
#define FL_SMEM ((3*128*QSTR + 128*PSTR)*4)

__global__ __launch_bounds__(256, 1)
void flash_attn(const float* __restrict__ q, const float* __restrict__ k,
                const float* __restrict__ v, float* __restrict__ o) {
    extern __shared__ float sm[];
    float* Qs = sm;
    float* Ks = sm + 128*QSTR;
    float* Vs = sm + 2*128*QSTR;
    float* Ps = sm + 3*128*QSTR;

    int qt = blockIdx.x, bh = blockIdx.y;
    int b = bh >> 4, h = bh & 15;
    int tid = threadIdx.x, warp = tid >> 5, lane = tid & 31;
    int grp = lane >> 2, tig = lane & 3;

    const float* qb = q + ((size_t)b*SEQ + qt*128) * Dm + h*DHd;
    const float* kb = k + (size_t)b*SEQ*Dm + h*DHd;
    const float* vb = v + (size_t)b*SEQ*Dm + h*DHd;

    // load Q tile (rna-converted tf32 bits stored as float)
    {
        int row = tid >> 1, c0 = (tid & 1) * 32;
        const float4* src = (const float4*)(qb + (size_t)row * Dm + c0);
        float* dst = Qs + row*QSTR + c0;
        #pragma unroll
        for (int i = 0; i < 8; i++) {
            float4 t4 = src[i];
            dst[i*4+0] = __uint_as_float(f2tf32(t4.x));
            dst[i*4+1] = __uint_as_float(f2tf32(t4.y));
            dst[i*4+2] = __uint_as_float(f2tf32(t4.z));
            dst[i*4+3] = __uint_as_float(f2tf32(t4.w));
        }
    }
    __syncthreads();

    // Q fragments live in registers (K=64 -> 8 ksteps)
    uint32_t qf[8][4];
    {
        const float* p = Qs + (warp*16 + grp) * QSTR;
        #pragma unroll
        for (int d0 = 0; d0 < 8; d0++) {
            qf[d0][0] = __float_as_uint(p[d0*8 + tig]);
            qf[d0][1] = __float_as_uint(p[8*QSTR + d0*8 + tig]);
            qf[d0][2] = __float_as_uint(p[d0*8 + tig + 4]);
            qf[d0][3] = __float_as_uint(p[8*QSTR + d0*8 + tig + 4]);
        }
    }

    float oacc[8][4] = {};
    float m0 = -1e30f, m1 = -1e30f, l0 = 0.f, l1 = 0.f;
    const float Csc = SCALE_ATTN * 1.4426950408889634f;   // softmax in log2 domain
    int prow = warp*16 + grp;

    for (int kv0 = 0; kv0 < SEQ; kv0 += 128) {
        // load K,V tiles (rna tf32)
        {
            int row = tid >> 1, c0 = (tid & 1) * 32;
            const float4* ksrc = (const float4*)(kb + (size_t)(kv0+row) * Dm + c0);
            const float4* vsrc = (const float4*)(vb + (size_t)(kv0+row) * Dm + c0);
            float* kd = Ks + row*QSTR + c0;
            float* vd = Vs + row*QSTR + c0;
            #pragma unroll
            for (int i = 0; i < 8; i++) {
                float4 t4 = ksrc[i];
                kd[i*4+0] = __uint_as_float(f2tf32(t4.x));
                kd[i*4+1] = __uint_as_float(f2tf32(t4.y));
                kd[i*4+2] = __uint_as_float(f2tf32(t4.z));
                kd[i*4+3] = __uint_as_float(f2tf32(t4.w));
                float4 u4 = vsrc[i];
                vd[i*4+0] = __uint_as_float(f2tf32(u4.x));
                vd[i*4+1] = __uint_as_float(f2tf32(u4.y));
                vd[i*4+2] = __uint_as_float(f2tf32(u4.z));
                vd[i*4+3] = __uint_as_float(f2tf32(u4.w));
            }
        }
        __syncthreads();

        // S = Q K^T (16x128 per warp)
        float sacc[16][4] = {};
        #pragma unroll
        for (int d0 = 0; d0 < 8; d0++) {
            #pragma unroll
            for (int nf = 0; nf < 16; nf++) {
                const float* kp = Ks + (nf*8 + grp) * QSTR + d0*8;
                uint32_t b0 = __float_as_uint(kp[tig]);
                uint32_t b1 = __float_as_uint(kp[tig + 4]);
                mma_tf32(sacc[nf], qf[d0][0], qf[d0][1], qf[d0][2], qf[d0][3], b0, b1);
            }
        }
        // online softmax (log2 domain)
        float mx0 = -1e30f, mx1 = -1e30f;
        #pragma unroll
        for (int nf = 0; nf < 16; nf++) {
            sacc[nf][0] *= Csc; sacc[nf][1] *= Csc; sacc[nf][2] *= Csc; sacc[nf][3] *= Csc;
            mx0 = fmaxf(mx0, fmaxf(sacc[nf][0], sacc[nf][1]));
            mx1 = fmaxf(mx1, fmaxf(sacc[nf][2], sacc[nf][3]));
        }
        mx0 = fmaxf(mx0, __shfl_xor_sync(0xffffffffu, mx0, 1));
        mx0 = fmaxf(mx0, __shfl_xor_sync(0xffffffffu, mx0, 2));
        mx1 = fmaxf(mx1, __shfl_xor_sync(0xffffffffu, mx1, 1));
        mx1 = fmaxf(mx1, __shfl_xor_sync(0xffffffffu, mx1, 2));
        float mn0 = fmaxf(m0, mx0), mn1 = fmaxf(m1, mx1);
        float sc0 = ex2f(m0 - mn0), sc1 = ex2f(m1 - mn1);
        float sum0 = 0.f, sum1 = 0.f;
        #pragma unroll
        for (int nf = 0; nf < 16; nf++) {
            float p0 = ex2f(sacc[nf][0] - mn0);
            float p1 = ex2f(sacc[nf][1] - mn0);
            float p2 = ex2f(sacc[nf][2] - mn1);
            float p3 = ex2f(sacc[nf][3] - mn1);
            sum0 += p0 + p1; sum1 += p2 + p3;
            int pc = nf*8 + tig*2;
            *(float2*)(Ps + prow*PSTR + pc) =
                make_float2(__uint_as_float(f2tf32(p0)), __uint_as_float(f2tf32(p1)));
            *(float2*)(Ps + (prow+8)*PSTR + pc) =
                make_float2(__uint_as_float(f2tf32(p2)), __uint_as_float(f2tf32(p3)));
        }
        sum0 += __shfl_xor_sync(0xffffffffu, sum0, 1);
        sum0 += __shfl_xor_sync(0xffffffffu, sum0, 2);
        sum1 += __shfl_xor_sync(0xffffffffu, sum1, 1);
        sum1 += __shfl_xor_sync(0xffffffffu, sum1, 2);
        l0 = l0 * sc0 + sum0;  l1 = l1 * sc1 + sum1;
        m0 = mn0;  m1 = mn1;
        #pragma unroll
        for (int nf = 0; nf < 8; nf++) {
            oacc[nf][0] *= sc0; oacc[nf][1] *= sc0;
            oacc[nf][2] *= sc1; oacc[nf][3] *= sc1;
        }
        __syncwarp();

        // O += P V  (warp reads only its own 16 P rows)
        #pragma unroll
        for (int ks = 0; ks < 128; ks += 8) {
            uint32_t a0 = __float_as_uint(Ps[prow*PSTR + ks + tig]);
            uint32_t a1 = __float_as_uint(Ps[(prow+8)*PSTR + ks + tig]);
            uint32_t a2 = __float_as_uint(Ps[prow*PSTR + ks + tig + 4]);
            uint32_t a3 = __float_as_uint(Ps[(prow+8)*PSTR + ks + tig + 4]);
            #pragma unroll
            for (int nf = 0; nf < 8; nf++) {
                uint32_t b0 = __float_as_uint(Vs[(ks + tig    ) * QSTR + nf*8 + grp]);
                uint32_t b1 = __float_as_uint(Vs[(ks + tig + 4) * QSTR + nf*8 + grp]);
                mma_tf32(oacc[nf], a0, a1, a2, a3, b0, b1);
            }
        }
        __syncthreads();
    }

    float i0 = 1.f / l0, i1 = 1.f / l1;
    float* ob = o + ((size_t)b*SEQ + qt*128 + warp*16) * Dm + h*DHd;
    #pragma unroll
    for (int nf = 0; nf < 8; nf++) {
        int c = nf*8 + tig*2;
        *(float2*)(ob + (size_t)grp * Dm + c) =
            make_float2(oacc[nf][0]*i0, oacc[nf][1]*i0);
        *(float2*)(ob + (size_t)(grp+8) * Dm + c) =
            make_float2(oacc[nf][2]*i1, oacc[nf][3]*i1);
    }
}

// ================= round-2 batched mma GEMM (kept for cross-attn) ============
#define SM_STRIDE 136
template<bool TRANSB>
__global__ __launch_bounds__(256)
void mma_gemm(const float* __restrict__ A, const float* __restrict__ B,
              const float* __restrict__ bias, const float* __restrict__ res,
              float* __restrict__ C,
              int M, int N, int K, int lda, int ldb, int ldc,
              long sAb, long sAh, long sBb, long sBh, long sCb, long sCh,
              int zdiv, float scale) {
    __shared__ uint32_t As[32][SM_STRIDE];
    __shared__ uint32_t Bs[32][SM_STRIDE];
    int z = blockIdx.z;
    const float* Ab = A + (size_t)(z / zdiv) * sAb + (size_t)(z % zdiv) * sAh;
    const float* Bb = B + (size_t)(z / zdiv) * sBb + (size_t)(z % zdiv) * sBh;
    float*       Cb = C + (size_t)(z / zdiv) * sCb + (size_t)(z % zdiv) * sCh;
    int bm = blockIdx.y * 128, bn = blockIdx.x * 128;
    int tid = threadIdx.x;
    int warp = tid >> 5, lane = tid & 31;
    int grp = lane >> 2, tig = lane & 3;
    int wm = (warp >> 2) * 64;
    int wn = (warp & 3) * 32;
    float acc[4][4][4] = {};
    bool ldaVec = ((lda & 3) == 0);
    bool ldbVec = ((ldb & 3) == 0);
    for (int k0 = 0; k0 < K; k0 += 32) {
        if (k0 + 32 <= K && ldaVec) {
            int kq = tid & 7, r0 = tid >> 3;
            #pragma unroll
            for (int stp = 0; stp < 4; stp++) {
                int row = r0 + stp * 32;
                float4 v = make_float4(0.f, 0.f, 0.f, 0.f);
                if (bm + row < M)
                    v = *reinterpret_cast<const float4*>(Ab + (size_t)(bm + row) * lda + k0 + kq * 4);
                As[kq*4+0][row] = f2tf32(v.x);
                As[kq*4+1][row] = f2tf32(v.y);
                As[kq*4+2][row] = f2tf32(v.z);
                As[kq*4+3][row] = f2tf32(v.w);
            }
        } else {
            for (int idx = tid; idx < 128 * 32; idx += 256) {
                int m = idx >> 5, kk = idx & 31;
                float v = (bm + m < M && k0 + kk < K)
                          ? Ab[(size_t)(bm + m) * lda + k0 + kk] : 0.f;
                As[kk][m] = f2tf32(v);
            }
        }
        if (TRANSB) {
            if (k0 + 32 <= K && ldbVec) {
                int kq = tid & 7, n0 = tid >> 3;
                #pragma unroll
                for (int stp = 0; stp < 4; stp++) {
                    int n = n0 + stp * 32;
                    float4 v = make_float4(0.f, 0.f, 0.f, 0.f);
                    if (bn + n < N)
                        v = *reinterpret_cast<const float4*>(Bb + (size_t)(bn + n) * ldb + k0 + kq * 4);
                    Bs[kq*4+0][n] = f2tf32(v.x);
                    Bs[kq*4+1][n] = f2tf32(v.y);
                    Bs[kq*4+2][n] = f2tf32(v.z);
                    Bs[kq*4+3][n] = f2tf32(v.w);
                }
            } else {
                for (int idx = tid; idx < 128 * 32; idx += 256) {
                    int kk = idx & 31, n = idx >> 5;
                    float v = (bn + n < N && k0 + kk < K)
                              ? Bb[(size_t)(bn + n) * ldb + k0 + kk] : 0.f;
                    Bs[kk][n] = f2tf32(v);
                }
            }
        } else {
            if (k0 + 32 <= K && bn + 128 <= N && ldbVec) {
                int n4 = tid & 31, kr0 = tid >> 5;
                #pragma unroll
                for (int stp = 0; stp < 4; stp++) {
                    int kk = kr0 + stp * 8;
                    float4 v = *reinterpret_cast<const float4*>(Bb + (size_t)(k0 + kk) * ldb + bn + n4 * 4);
                    Bs[kk][n4*4+0] = f2tf32(v.x);
                    Bs[kk][n4*4+1] = f2tf32(v.y);
                    Bs[kk][n4*4+2] = f2tf32(v.z);
                    Bs[kk][n4*4+3] = f2tf32(v.w);
                }
            } else {
                for (int idx = tid; idx < 128 * 32; idx += 256) {
                    int n = idx & 127, kk = idx >> 7;
                    float v = (k0 + kk < K && bn + n < N)
                              ? Bb[(size_t)(k0 + kk) * ldb + bn + n] : 0.f;
                    Bs[kk][n] = f2tf32(v);
                }
            }
        }
        __syncthreads();
        #pragma unroll
        for (int ks = 0; ks < 32; ks += 8) {
            uint32_t a[4][4], b[4][2];
            #pragma unroll
            for (int mf = 0; mf < 4; mf++) {
                int m = wm + mf * 16 + grp;
                a[mf][0] = As[ks + tig    ][m];
                a[mf][1] = As[ks + tig    ][m + 8];
                a[mf][2] = As[ks + tig + 4][m];
                a[mf][3] = As[ks + tig + 4][m + 8];
            }
            #pragma unroll
            for (int nf = 0; nf < 4; nf++) {
                int n = wn + nf * 8 + grp;
                b[nf][0] = Bs[ks + tig    ][n];
                b[nf][1] = Bs[ks + tig + 4][n];
            }
            #pragma unroll
            for (int mf = 0; mf < 4; mf++)
                #pragma unroll
                for (int nf = 0; nf < 4; nf++)
                    mma_tf32(acc[mf][nf], a[mf][0], a[mf][1], a[mf][2], a[mf][3],
                             b[nf][0], b[nf][1]);
        }
        __syncthreads();
    }
    #pragma unroll
    for (int mf = 0; mf < 4; mf++) {
        #pragma unroll
        for (int nf = 0; nf < 4; nf++) {
            int r0 = bm + wm + mf * 16 + grp;
            int c0 = bn + wn + nf * 8 + tig * 2;
            #pragma unroll
            for (int e = 0; e < 4; e++) {
                int r = r0 + (e >> 1) * 8;
                int c = c0 + (e & 1);
                if (r < M && c < N) {
                    float v = acc[mf][nf][e] * scale;
                    if (bias) v += bias[c];
                    if (res)  v += res[(size_t)r * ldc + c];
                    Cb[(size_t)r * ldc + c] = v;
                }
            }
        }
    }
}

// ---------------- elementwise copy ----------------
__global__ void copy_kernel(const float* __restrict__ src, float* __restrict__ dst, int n4) {
    int i = blockIdx.x * blockDim.x + threadIdx.x;
    if (i < n4)
        reinterpret_cast<float4*>(dst)[i] = reinterpret_cast<const float4*>(src)[i];
}

// ---------------- layernorm ----------------
__global__ void ln_kernel(const float* __restrict__ x, const float* __restrict__ g,
                          const float* __restrict__ b, float* __restrict__ out) {
    int row = blockIdx.x;
    const float* xr = x + (size_t)row * Dm;
    float s = 0.f, ss = 0.f;
    for (int i = threadIdx.x; i < Dm; i += 256) {
        float v = xr[i];
        s += v; ss += v * v;
    }
    __shared__ float rs[256], rss[256];
    rs[threadIdx.x] = s; rss[threadIdx.x] = ss;
    __syncthreads();
    for (int st = 128; st > 0; st >>= 1) {
        if (threadIdx.x < st) { rs[threadIdx.x] += rs[threadIdx.x+st]; rss[threadIdx.x] += rss[threadIdx.x+st]; }
        __syncthreads();
    }
    float mu  = rs[0] * (1.0f / Dm);
    float var = rss[0] * (1.0f / Dm) - mu * mu;
    float inv = rsqrtf(var + EPS_LN);
    float* orow = out + (size_t)row * Dm;
    for (int i = threadIdx.x; i < Dm; i += 256)
        orow[i] = (xr[i] - mu) * inv * g[i] + b[i];
}

// ---------------- fp32 fallback GEMM (tiny cross-KV proj) ----------------
__global__ void gemm_kernel(const float* __restrict__ A, const float* __restrict__ Bm,
                            const float* __restrict__ bias, const float* __restrict__ res,
                            float* __restrict__ C, int M, int K, int Nn) {
    __shared__ float As[64][17];
    __shared__ float Bs[16][64];
    int bm = blockIdx.y * 64, bn = blockIdx.x * 64;
    int tx = threadIdx.x & 15, ty = threadIdx.x >> 4;
    float acc[4][4] = {};
    for (int k0 = 0; k0 < K; k0 += 16) {
        #pragma unroll
        for (int i = 0; i < 4; i++) {
            int idx = threadIdx.x + i * 256;
            int r = idx >> 4, kk = idx & 15;
            int gr = bm + r;
            As[r][kk] = (gr < M) ? A[(size_t)gr * K + k0 + kk] : 0.f;
            int kb = idx >> 6, c = idx & 63;
            int gc = bn + c;
            Bs[kb][c] = (gc < Nn) ? Bm[(size_t)(k0 + kb) * Nn + gc] : 0.f;
        }
        __syncthreads();
        #pragma unroll
        for (int kk = 0; kk < 16; kk++) {
            float a[4], bb[4];
            #pragma unroll
            for (int i = 0; i < 4; i++) a[i]  = As[ty*4+i][kk];
            #pragma unroll
            for (int j = 0; j < 4; j++) bb[j] = Bs[kk][tx*4+j];
            #pragma unroll
            for (int i = 0; i < 4; i++)
                #pragma unroll
                for (int j = 0; j < 4; j++)
                    acc[i][j] += a[i] * bb[j];
        }
        __syncthreads();
    }
    #pragma unroll
    for (int i = 0; i < 4; i++) {
        int gr = bm + ty*4 + i;
        if (gr >= M) continue;
        #pragma unroll
        for (int j = 0; j < 4; j++) {
            int gc = bn + tx*4 + j;
            if (gc >= Nn) continue;
            float v = acc[i][j];
            if (bias) v += bias[gc];
            if (res)  v += res[(size_t)gr * Nn + gc];
            C[(size_t)gr * Nn + gc] = v;
        }
    }
}

// ---------------- row softmax ----------------
__global__ void softmax_kernel(float* __restrict__ s, int len) {
    float* r = s + (size_t)blockIdx.x * len;
    __shared__ float red[256];
    float mx = -3.4e38f;
    for (int i = threadIdx.x; i < len; i += 256) mx = fmaxf(mx, r[i]);
    red[threadIdx.x] = mx; __syncthreads();
    for (int st = 128; st > 0; st >>= 1) {
        if (threadIdx.x < st) red[threadIdx.x] = fmaxf(red[threadIdx.x], red[threadIdx.x+st]);
        __syncthreads();
    }
    mx = red[0];
    __syncthreads();
    float sum = 0.f;
    for (int i = threadIdx.x; i < len; i += 256) {
        float e = expf(r[i] - mx);
        r[i] = e;
        sum += e;
    }
    red[threadIdx.x] = sum; __syncthreads();
    for (int st = 128; st > 0; st >>= 1) {
        if (threadIdx.x < st) red[threadIdx.x] += red[threadIdx.x+st];
        __syncthreads();
    }
    float inv = 1.f / red[0];
    for (int i = threadIdx.x; i < len; i += 256) r[i] *= inv;
}

// ---------------- GEGLU ----------------
__global__ void geglu_kernel(const float* __restrict__ p, float* __restrict__ t) {
    size_t idx = (size_t)blockIdx.x * blockDim.x + threadIdx.x;
    if (idx < (size_t)MROWS * FFd) {
        size_t row = idx / FFd, col = idx % FFd;
        float val  = p[row * (2*FFd) + col];
        float gate = p[row * (2*FFd) + FFd + col];
        float ge = 0.5f * gate * (1.f + erff(gate * 0.70710678118654752f));
        t[idx] = val * ge;
    }
}

// ---------------- launch ----------------
extern "C" void kernel_launch(void* const* d_in, const int* in_sizes, int n_in,
                              void* d_out, int out_size) {
    const float* x      = (const float*)d_in[0];
    const float* ctx    = (const float*)d_in[1];
    const float* w1_q   = (const float*)d_in[2];
    const float* w1_k   = (const float*)d_in[3];
    const float* w1_v   = (const float*)d_in[4];
    const float* w1_o   = (const float*)d_in[5];
    const float* b1_o   = (const float*)d_in[6];
    const float* w2_q   = (const float*)d_in[7];
    const float* w2_k   = (const float*)d_in[8];
    const float* w2_v   = (const float*)d_in[9];
    const float* w2_o   = (const float*)d_in[10];
    const float* b2_o   = (const float*)d_in[11];
    const float* ln1_g  = (const float*)d_in[12];
    const float* ln1_b  = (const float*)d_in[13];
    const float* ln2_g  = (const float*)d_in[14];
    const float* ln2_b  = (const float*)d_in[15];
    const float* ln3_g  = (const float*)d_in[16];
    const float* ln3_b  = (const float*)d_in[17];
    const float* ff_w1  = (const float*)d_in[18];
    const float* ff_b1  = (const float*)d_in[19];
    const float* ff_w2  = (const float*)d_in[20];
    const float* ff_b2  = (const float*)d_in[21];
    float* xbuf = (float*)d_out;

    float *hB, *qB, *kB, *vB, *attB, *sB, *pB, *tB;
    cudaGetSymbolAddress((void**)&hB,   g_h);
    cudaGetSymbolAddress((void**)&qB,   g_q);
    cudaGetSymbolAddress((void**)&kB,   g_k);
    cudaGetSymbolAddress((void**)&vB,   g_v);
    cudaGetSymbolAddress((void**)&attB, g_att);
    cudaGetSymbolAddress((void**)&sB,   g_s);
    cudaGetSymbolAddress((void**)&pB,   g_p);
    cudaGetSymbolAddress((void**)&tB,   g_t);

    cudaFuncSetAttribute(gemm_fast,  cudaFuncAttributeMaxDynamicSharedMemorySize, GF_SMEM);
    cudaFuncSetAttribute(flash_attn, cudaFuncAttributeMaxDynamicSharedMemorySize, FL_SMEM);

    dim3 gD(Dm/128, MROWS/128);             // 8 x 32
    dim3 gFF1(2*FFd/128, MROWS/128);        // 64 x 32
    dim3 gFlash(SEQ/128, Bq*Hh);            // 16 x 32
    dim3 gScoresCross(1, SEQ/128, Bq*Hh);
    dim3 gAVc(1, SEQ/128, Bq*Hh);

    copy_kernel<<<(MROWS*Dm/4 + 255)/256, 256>>>(x, xbuf, MROWS*Dm/4);

    // ---- self attention (flash) ----
    ln_kernel<<<MROWS, 256>>>(xbuf, ln1_g, ln1_b, hB);
    gemm_fast<<<gD, 128, GF_SMEM>>>(hB, w1_q, nullptr, nullptr, qB, MROWS, Dm, Dm);
    gemm_fast<<<gD, 128, GF_SMEM>>>(hB, w1_k, nullptr, nullptr, kB, MROWS, Dm, Dm);
    gemm_fast<<<gD, 128, GF_SMEM>>>(hB, w1_v, nullptr, nullptr, vB, MROWS, Dm, Dm);
    flash_attn<<<gFlash, 256, FL_SMEM>>>(qB, kB, vB, attB);
    gemm_fast<<<gD, 128, GF_SMEM>>>(attB, w1_o, b1_o, xbuf, xbuf, MROWS, Dm, Dm);

    // ---- cross attention (round-2 path; nk=77 is tiny) ----
    ln_kernel<<<MROWS, 256>>>(xbuf, ln2_g, ln2_b, hB);
    gemm_fast<<<gD, 128, GF_SMEM>>>(hB, w2_q, nullptr, nullptr, qB, MROWS, Dm, Dm);
    dim3 gKV(Dm/64, (CROWS+63)/64);
    gemm_kernel<<<gKV, 256>>>(ctx, w2_k, nullptr, nullptr, kB, CROWS, DCx, Dm);
    gemm_kernel<<<gKV, 256>>>(ctx, w2_v, nullptr, nullptr, vB, CROWS, DCx, Dm);
    mma_gemm<true><<<gScoresCross, 256>>>(qB, kB, nullptr, nullptr, sB,
                                 SEQ, NCx, DHd, Dm, Dm, NCx,
                                 (long)SEQ*Dm, DHd, (long)NCx*Dm, DHd,
                                 (long)Hh*SEQ*NCx, (long)SEQ*NCx, Hh, SCALE_ATTN);
    softmax_kernel<<<Bq*Hh*SEQ, 256>>>(sB, NCx);
    mma_gemm<false><<<gAVc, 256>>>(sB, vB, nullptr, nullptr, attB,
                                 SEQ, DHd, NCx, NCx, Dm, Dm,
                                 (long)Hh*SEQ*NCx, (long)SEQ*NCx, (long)NCx*Dm, DHd,
                                 (long)SEQ*Dm, DHd, Hh, 1.f);
    gemm_fast<<<gD, 128, GF_SMEM>>>(attB, w2_o, b2_o, xbuf, xbuf, MROWS, Dm, Dm);

    // ---- GEGLU FFN ----
    ln_kernel<<<MROWS, 256>>>(xbuf, ln3_g, ln3_b, hB);
    gemm_fast<<<gFF1, 128, GF_SMEM>>>(hB, ff_w1, ff_b1, nullptr, pB, MROWS, 2*FFd, Dm);
    geglu_kernel<<<((size_t)MROWS*FFd + 255)/256, 256>>>(pB, tB);
    gemm_fast<<<gD, 128, GF_SMEM>>>(tB, ff_w2, ff_b2, xbuf, xbuf, MROWS, Dm, FFd);
}